// round 7
// baseline (speedup 1.0000x reference)
#include <cuda_runtime.h>
#include <cstdint>
#include <math_constants.h>

// B=64, I=1024, O=1024, et in {0,1,2}
// tnorm (op==0): val = (et==2 ? 1-x : x) + (et==0 ? +10 : 0), reduce = min
// tconorm:       same with -10, reduce = max
// Sign trick: s = tnorm ? +1 : -1.  w = s*v = (et==2 ? s - s*x : s*x) + (et==0 ? 10 : 0)
//   answer = s * min(w)   (exact; s*offset = +10 in both cases)

#define B_DIM 64
#define I_DIM 1024
#define O_DIM 1024
#define THREADS 256
#define ROWS_PER_TILE 16                 // 8 warps * 2 rows
#define GROUPS_PER_B (O_DIM / ROWS_PER_TILE)   // 64

// min over 16 elements of w = s*v for one half-batch; x values in registers.
static __device__ __forceinline__
float half_row_min(const int4* __restrict__ e, const float4* __restrict__ xv,
                   float s)
{
    float red = CUDART_INF_F;
    #pragma unroll
    for (int j = 0; j < 4; ++j) {
        float t0 = s * xv[j].x, t1 = s * xv[j].y, t2 = s * xv[j].z, t3 = s * xv[j].w;
        float v0 = (e[j].x == 2) ? (s - t0) : t0;
        float v1 = (e[j].y == 2) ? (s - t1) : t1;
        float v2 = (e[j].z == 2) ? (s - t2) : t2;
        float v3 = (e[j].w == 2) ? (s - t3) : t3;
        if (e[j].x == 0) v0 += 10.0f;
        if (e[j].y == 0) v1 += 10.0f;
        if (e[j].z == 0) v2 += 10.0f;
        if (e[j].w == 0) v3 += 10.0f;
        red = fminf(red, fminf(fminf(v0, v1), fminf(v2, v3)));
    }
    return red;
}

static __device__ __forceinline__
float warp_min(float red)
{
    #pragma unroll
    for (int sh = 16; sh > 0; sh >>= 1)
        red = fminf(red, __shfl_xor_sync(0xffffffffu, red, sh));
    return red;
}

__global__ void __launch_bounds__(THREADS, 2)
ffcl_kernel(const float* __restrict__ x,
            const int4* __restrict__ et4,
            const int* __restrict__ op_idx,
            float* __restrict__ out)
{
    const int b = blockIdx.x >> 6;              // / GROUPS_PER_B
    const int g = blockIdx.x & (GROUPS_PER_B - 1);

    const int warp = threadIdx.x >> 5;
    const int lane = threadIdx.x & 31;
    const int o0   = g * ROWS_PER_TILE + warp * 2;

    const int4* rowp = et4 + (size_t)(b * O_DIM + o0) * (I_DIM / 4);

    // ---- Prologue: et stream starts immediately (depth-2: 8 LDG.128 in flight).
    int4 A[4], Bv[4], C[4];
    #pragma unroll
    for (int j = 0; j < 4; ++j)                  // H0: row0 first half
        A[j] = __ldcs(rowp + j * 32 + lane);
    #pragma unroll
    for (int j = 0; j < 4; ++j)                  // H1: row0 second half
        Bv[j] = __ldcs(rowp + 128 + j * 32 + lane);

    // x values this lane ever needs: fixed positions, 8 float4 in registers.
    // x is 256 KB -> L2-resident; these overlap the in-flight et loads.
    const float4* xrow4 = reinterpret_cast<const float4*>(x + (size_t)b * I_DIM);
    float4 xlo[4], xhi[4];
    #pragma unroll
    for (int j = 0; j < 4; ++j) {
        xlo[j] = __ldg(xrow4 + j * 32 + lane);
        xhi[j] = __ldg(xrow4 + 128 + j * 32 + lane);
    }

    const float s0 = (op_idx[o0]     == 0) ? 1.0f : -1.0f;
    const float s1 = (op_idx[o0 + 1] == 0) ? 1.0f : -1.0f;

    // ---- Steady state: barrier-free, no shared memory.
    #pragma unroll
    for (int j = 0; j < 4; ++j)                  // H2: row1 first half
        C[j] = __ldcs(rowp + 256 + j * 32 + lane);

    float red0 = half_row_min(A, xlo, s0);

    #pragma unroll
    for (int j = 0; j < 4; ++j)                  // H3: row1 second half
        A[j] = __ldcs(rowp + 384 + j * 32 + lane);

    red0 = fminf(red0, half_row_min(Bv, xhi, s0));
    red0 = warp_min(red0);
    if (lane == 0)
        out[(size_t)b * O_DIM + o0] = s0 * red0;

    float red1 = half_row_min(C, xlo, s1);
    red1 = fminf(red1, half_row_min(A, xhi, s1));
    red1 = warp_min(red1);
    if (lane == 0)
        out[(size_t)b * O_DIM + o0 + 1] = s1 * red1;
}

extern "C" void kernel_launch(void* const* d_in, const int* in_sizes, int n_in,
                              void* d_out, int out_size)
{
    (void)in_sizes; (void)n_in; (void)out_size;
    const float* x      = (const float*)d_in[0];
    const int4*  et4    = (const int4*)d_in[1];
    const int*   op_idx = (const int*)d_in[2];
    float*       out    = (float*)d_out;

    const int blocks = B_DIM * GROUPS_PER_B;    // 4096
    ffcl_kernel<<<blocks, THREADS>>>(x, et4, op_idx, out);
}

// round 8
// speedup vs baseline: 1.0859x; 1.0859x over previous
#include <cuda_runtime.h>
#include <cstdint>
#include <math_constants.h>

// B=64, I=1024, O=1024, et in {0,1,2}
// tnorm (op==0): val = (et==2 ? 1-x : x) + (et==0 ? +10 : 0), reduce = min
// tconorm:       same with -10, reduce = max
// Sign trick: s = tnorm ? +1 : -1.  w = s*v = (et==2 ? s - s*x : s*x) + (et==0 ? 10 : 0)
//   answer = s * min(w)   (exact; s*offset = +10 in both cases)

#define B_DIM 64
#define I_DIM 1024
#define O_DIM 1024
#define THREADS 256
#define ROWS_PER_TILE 16                 // 8 warps * 2 rows
#define GROUPS_PER_B (O_DIM / ROWS_PER_TILE)   // 64

// 256-bit global load (sm_100a+/sm_103a): 8 x b32 in one LDG.E.256.
static __device__ __forceinline__
void ldg256(uint32_t* r, const void* p)
{
    asm volatile("ld.global.v8.b32 {%0,%1,%2,%3,%4,%5,%6,%7}, [%8];"
                 : "=r"(r[0]), "=r"(r[1]), "=r"(r[2]), "=r"(r[3]),
                   "=r"(r[4]), "=r"(r[5]), "=r"(r[6]), "=r"(r[7])
                 : "l"(p));
}

// min of w = s*v over one 8-element chunk (8 et ints + 2 float4 of x).
static __device__ __forceinline__
float chunk_min(const uint32_t* __restrict__ e, float4 a, float4 b, float s)
{
    float t0 = s * a.x, t1 = s * a.y, t2 = s * a.z, t3 = s * a.w;
    float t4 = s * b.x, t5 = s * b.y, t6 = s * b.z, t7 = s * b.w;
    float v0 = ((int)e[0] == 2) ? (s - t0) : t0;
    float v1 = ((int)e[1] == 2) ? (s - t1) : t1;
    float v2 = ((int)e[2] == 2) ? (s - t2) : t2;
    float v3 = ((int)e[3] == 2) ? (s - t3) : t3;
    float v4 = ((int)e[4] == 2) ? (s - t4) : t4;
    float v5 = ((int)e[5] == 2) ? (s - t5) : t5;
    float v6 = ((int)e[6] == 2) ? (s - t6) : t6;
    float v7 = ((int)e[7] == 2) ? (s - t7) : t7;
    if ((int)e[0] == 0) v0 += 10.0f;
    if ((int)e[1] == 0) v1 += 10.0f;
    if ((int)e[2] == 0) v2 += 10.0f;
    if ((int)e[3] == 0) v3 += 10.0f;
    if ((int)e[4] == 0) v4 += 10.0f;
    if ((int)e[5] == 0) v5 += 10.0f;
    if ((int)e[6] == 0) v6 += 10.0f;
    if ((int)e[7] == 0) v7 += 10.0f;
    float m01 = fminf(v0, v1), m23 = fminf(v2, v3);
    float m45 = fminf(v4, v5), m67 = fminf(v6, v7);
    return fminf(fminf(m01, m23), fminf(m45, m67));
}

// min over a full row (4 chunks of 32 B per lane), x from shared.
static __device__ __forceinline__
float row_min(const uint32_t E[4][8], const float4* __restrict__ xs4,
              int lane, float s)
{
    float red = CUDART_INF_F;
    #pragma unroll
    for (int j = 0; j < 4; ++j) {
        const int idx = j * 32 + lane;
        red = fminf(red, chunk_min(E[j], xs4[2 * idx], xs4[2 * idx + 1], s));
    }
    return red;
}

static __device__ __forceinline__
float warp_min(float red)
{
    #pragma unroll
    for (int sh = 16; sh > 0; sh >>= 1)
        red = fminf(red, __shfl_xor_sync(0xffffffffu, red, sh));
    return red;
}

__global__ void __launch_bounds__(THREADS, 4)
ffcl_kernel(const float* __restrict__ x,
            const int* __restrict__ et,
            const int* __restrict__ op_idx,
            float* __restrict__ out)
{
    __shared__ float xs[I_DIM];

    const int b = blockIdx.x >> 6;              // / GROUPS_PER_B
    const int g = blockIdx.x & (GROUPS_PER_B - 1);

    const int warp = threadIdx.x >> 5;
    const int lane = threadIdx.x & 31;
    const int o0   = g * ROWS_PER_TILE + warp * 2;

    const char* rowp = reinterpret_cast<const char*>(
        et + (size_t)(b * O_DIM + o0) * I_DIM);

    // ---- Prologue: row0's 4 LDG.256 first (et stream starts immediately).
    uint32_t E0[4][8], E1[4][8];
    #pragma unroll
    for (int j = 0; j < 4; ++j)
        ldg256(E0[j], rowp + (size_t)(j * 32 + lane) * 32);

    // Stage x[b,:] into shared (4 KB): one float4 per thread; overlaps et loads.
    reinterpret_cast<float4*>(xs)[threadIdx.x] =
        reinterpret_cast<const float4*>(x + (size_t)b * I_DIM)[threadIdx.x];

    // Row1's 4 LDG.256: in flight through row0's compute.
    #pragma unroll
    for (int j = 0; j < 4; ++j)
        ldg256(E1[j], rowp + 4096 + (size_t)(j * 32 + lane) * 32);

    const float s0 = (op_idx[o0]     == 0) ? 1.0f : -1.0f;
    const float s1 = (op_idx[o0 + 1] == 0) ? 1.0f : -1.0f;

    __syncthreads();
    const float4* xs4 = reinterpret_cast<const float4*>(xs);

    // ---- Steady state: barrier-free.
    float red0 = warp_min(row_min(E0, xs4, lane, s0));
    if (lane == 0)
        out[(size_t)b * O_DIM + o0] = s0 * red0;

    float red1 = warp_min(row_min(E1, xs4, lane, s1));
    if (lane == 0)
        out[(size_t)b * O_DIM + o0 + 1] = s1 * red1;
}

extern "C" void kernel_launch(void* const* d_in, const int* in_sizes, int n_in,
                              void* d_out, int out_size)
{
    (void)in_sizes; (void)n_in; (void)out_size;
    const float* x      = (const float*)d_in[0];
    const int*   et     = (const int*)d_in[1];
    const int*   op_idx = (const int*)d_in[2];
    float*       out    = (float*)d_out;

    const int blocks = B_DIM * GROUPS_PER_B;    // 4096
    ffcl_kernel<<<blocks, THREADS>>>(x, et, op_idx, out);
}

// round 9
// speedup vs baseline: 1.0928x; 1.0063x over previous
#include <cuda_runtime.h>
#include <cstdint>
#include <math_constants.h>

// B=64, I=1024, O=1024, et in {0,1,2}
// tnorm (op==0): val = (et==2 ? 1-x : x) + (et==0 ? +10 : 0), reduce = min
// tconorm:       same with -10, reduce = max
// Sign trick: s = tnorm ? +1 : -1.  w = s*v = (et==2 ? s - s*x : s*x) + (et==0 ? 10 : 0)
//   answer = s * min(w)   (exact; s*offset = +10 in both cases)

#define B_DIM 64
#define I_DIM 1024
#define O_DIM 1024
#define THREADS 128
#define WARPS_PB 4
#define ROWS_PER_WARP 2
#define ROWS_PER_BLOCK (WARPS_PB * ROWS_PER_WARP)      // 8
#define GROUPS_PER_B (O_DIM / ROWS_PER_BLOCK)          // 128
#define ROW_BYTES (I_DIM * 4)                          // 4096

static __device__ __forceinline__ uint32_t smem_u32(const void* p)
{
    return (uint32_t)__cvta_generic_to_shared(p);
}

static __device__ __forceinline__ void mbar_init(uint32_t addr, uint32_t cnt)
{
    asm volatile("mbarrier.init.shared.b64 [%0], %1;" :: "r"(addr), "r"(cnt) : "memory");
}

static __device__ __forceinline__ void mbar_expect_tx(uint32_t addr, uint32_t bytes)
{
    asm volatile("mbarrier.arrive.expect_tx.shared.b64 _, [%0], %1;"
                 :: "r"(addr), "r"(bytes) : "memory");
}

static __device__ __forceinline__ void bulk_g2s(uint32_t dst, const void* src,
                                                uint32_t bytes, uint32_t mbar)
{
    asm volatile("cp.async.bulk.shared::cta.global.mbarrier::complete_tx::bytes "
                 "[%0], [%1], %2, [%3];"
                 :: "r"(dst), "l"(src), "r"(bytes), "r"(mbar) : "memory");
}

static __device__ __forceinline__ void mbar_wait(uint32_t addr, uint32_t parity)
{
    asm volatile(
        "{\n\t"
        ".reg .pred P;\n\t"
        "WAIT_%=:\n\t"
        "mbarrier.try_wait.parity.acquire.cta.shared::cta.b64 P, [%0], %1, 0x989680;\n\t"
        "@P bra DONE_%=;\n\t"
        "bra WAIT_%=;\n\t"
        "DONE_%=:\n\t"
        "}"
        :: "r"(addr), "r"(parity) : "memory");
}

// min of w = s*v over one row (256 int4 in smem + 256 float4 of x in smem).
static __device__ __forceinline__
float row_min_smem(const int4* __restrict__ e4, const float4* __restrict__ xs4,
                   int lane, float s)
{
    float red = CUDART_INF_F;
    #pragma unroll
    for (int j = 0; j < 8; ++j) {
        const int idx = j * 32 + lane;
        const int4   e  = e4[idx];
        const float4 xv = xs4[idx];
        float t0 = s * xv.x, t1 = s * xv.y, t2 = s * xv.z, t3 = s * xv.w;
        float v0 = (e.x == 2) ? (s - t0) : t0;
        float v1 = (e.y == 2) ? (s - t1) : t1;
        float v2 = (e.z == 2) ? (s - t2) : t2;
        float v3 = (e.w == 2) ? (s - t3) : t3;
        if (e.x == 0) v0 += 10.0f;
        if (e.y == 0) v1 += 10.0f;
        if (e.z == 0) v2 += 10.0f;
        if (e.w == 0) v3 += 10.0f;
        red = fminf(red, fminf(fminf(v0, v1), fminf(v2, v3)));
    }
    return red;
}

static __device__ __forceinline__
float warp_min(float red)
{
    #pragma unroll
    for (int sh = 16; sh > 0; sh >>= 1)
        red = fminf(red, __shfl_xor_sync(0xffffffffu, red, sh));
    return red;
}

__global__ void __launch_bounds__(THREADS, 6)
ffcl_kernel(const float* __restrict__ x,
            const int* __restrict__ et,
            const int* __restrict__ op_idx,
            float* __restrict__ out)
{
    __shared__ float xs[I_DIM];                         // 4 KB
    __shared__ __align__(16) int4 ets[WARPS_PB][2][I_DIM / 4];  // 32 KB
    __shared__ __align__(8) uint64_t mbar[WARPS_PB][2];

    const int b = blockIdx.x >> 7;                      // / GROUPS_PER_B
    const int g = blockIdx.x & (GROUPS_PER_B - 1);

    const int warp = threadIdx.x >> 5;
    const int lane = threadIdx.x & 31;
    const int o0   = g * ROWS_PER_BLOCK + warp * ROWS_PER_WARP;

    if (lane == 0) {
        mbar_init(smem_u32(&mbar[warp][0]), 1);
        mbar_init(smem_u32(&mbar[warp][1]), 1);
    }

    // Stage x[b,:] into shared: 256 float4 by 128 threads.
    {
        const float4* xr = reinterpret_cast<const float4*>(x + (size_t)b * I_DIM);
        float4* xw = reinterpret_cast<float4*>(xs);
        xw[threadIdx.x]       = xr[threadIdx.x];
        xw[threadIdx.x + 128] = xr[threadIdx.x + 128];
    }
    __syncthreads();

    // Issue both bulk copies per warp: 8 KB in flight immediately, no regs.
    const int* rowp = et + (size_t)(b * O_DIM + o0) * I_DIM;
    if (lane == 0) {
        asm volatile("fence.proxy.async.shared::cta;" ::: "memory");
        const uint32_t m0 = smem_u32(&mbar[warp][0]);
        const uint32_t m1 = smem_u32(&mbar[warp][1]);
        mbar_expect_tx(m0, ROW_BYTES);
        bulk_g2s(smem_u32(ets[warp][0]), rowp, ROW_BYTES, m0);
        mbar_expect_tx(m1, ROW_BYTES);
        bulk_g2s(smem_u32(ets[warp][1]), rowp + I_DIM, ROW_BYTES, m1);
    }

    const float s0 = (op_idx[o0]     == 0) ? 1.0f : -1.0f;
    const float s1 = (op_idx[o0 + 1] == 0) ? 1.0f : -1.0f;
    const float4* xs4 = reinterpret_cast<const float4*>(xs);

    // Row 0
    mbar_wait(smem_u32(&mbar[warp][0]), 0);
    float red0 = warp_min(row_min_smem(ets[warp][0], xs4, lane, s0));
    if (lane == 0)
        out[(size_t)b * O_DIM + o0] = s0 * red0;

    // Row 1
    mbar_wait(smem_u32(&mbar[warp][1]), 0);
    float red1 = warp_min(row_min_smem(ets[warp][1], xs4, lane, s1));
    if (lane == 0)
        out[(size_t)b * O_DIM + o0 + 1] = s1 * red1;
}

extern "C" void kernel_launch(void* const* d_in, const int* in_sizes, int n_in,
                              void* d_out, int out_size)
{
    (void)in_sizes; (void)n_in; (void)out_size;
    const float* x      = (const float*)d_in[0];
    const int*   et     = (const int*)d_in[1];
    const int*   op_idx = (const int*)d_in[2];
    float*       out    = (float*)d_out;

    const int blocks = B_DIM * GROUPS_PER_B;           // 8192
    ffcl_kernel<<<blocks, THREADS>>>(x, et, op_idx, out);
}

// round 10
// speedup vs baseline: 1.1943x; 1.0929x over previous
#include <cuda_runtime.h>
#include <cstdint>
#include <math_constants.h>

// B=64, I=1024, O=1024, et in {0,1,2}
// tnorm (op==0): val = (et==2 ? 1-x : x) + (et==0 ? +10 : 0), reduce = min
// tconorm:       same with -10, reduce = max
// Sign trick: s = tnorm ? +1 : -1.  w = s*v = (et==2 ? s - s*x : s*x) + (et==0 ? 10 : 0)
//   answer = s * min(w)   (exact; s*offset = +10 in both cases)

#define B_DIM 64
#define I_DIM 1024
#define O_DIM 1024
#define THREADS 128
#define WARPS_PB 4
#define ROWS_PER_BLOCK (WARPS_PB * 2)           // 8
#define GROUPS_PER_B (O_DIM / ROWS_PER_BLOCK)   // 128

static __device__ __forceinline__
float half_row_min(const int4* __restrict__ e, const float4* __restrict__ xs4,
                   int lane, float s)
{
    float red = CUDART_INF_F;
    #pragma unroll
    for (int j = 0; j < 4; ++j) {
        const float4 xv = xs4[j * 32 + lane];
        float t0 = s * xv.x, t1 = s * xv.y, t2 = s * xv.z, t3 = s * xv.w;
        float v0 = (e[j].x == 2) ? (s - t0) : t0;
        float v1 = (e[j].y == 2) ? (s - t1) : t1;
        float v2 = (e[j].z == 2) ? (s - t2) : t2;
        float v3 = (e[j].w == 2) ? (s - t3) : t3;
        if (e[j].x == 0) v0 += 10.0f;
        if (e[j].y == 0) v1 += 10.0f;
        if (e[j].z == 0) v2 += 10.0f;
        if (e[j].w == 0) v3 += 10.0f;
        red = fminf(red, fminf(fminf(v0, v1), fminf(v2, v3)));
    }
    return red;
}

static __device__ __forceinline__
float warp_min(float red)
{
    #pragma unroll
    for (int sh = 16; sh > 0; sh >>= 1)
        red = fminf(red, __shfl_xor_sync(0xffffffffu, red, sh));
    return red;
}

__global__ void __launch_bounds__(THREADS, 8)
ffcl_kernel(const float* __restrict__ x,
            const int4* __restrict__ et4,
            const int* __restrict__ op_idx,
            float* __restrict__ out)
{
    __shared__ float xs[I_DIM];                 // 4 KB

    const int b = blockIdx.x >> 7;              // / GROUPS_PER_B
    const int g = blockIdx.x & (GROUPS_PER_B - 1);

    const int warp = threadIdx.x >> 5;
    const int lane = threadIdx.x & 31;
    const int o0   = g * ROWS_PER_BLOCK + warp * 2;

    const int4* rowp = et4 + (size_t)(b * O_DIM + o0) * (I_DIM / 4);

    // ---- Prologue: 8 LDG.128 (row0 H0+H1) in flight BEFORE the barrier,
    //      so the barrier wait itself is covered by the et stream.
    int4 A[4], Bv[4];
    #pragma unroll
    for (int j = 0; j < 4; ++j)                  // H0: row0 first half
        A[j] = __ldcs(rowp + j * 32 + lane);
    #pragma unroll
    for (int j = 0; j < 4; ++j)                  // H1: row0 second half
        Bv[j] = __ldcs(rowp + 128 + j * 32 + lane);

    // Stage x[b,:] into shared: 2 float4 per thread (128 threads x 2 = 256).
    {
        const float4* xr = reinterpret_cast<const float4*>(x + (size_t)b * I_DIM);
        float4* xw = reinterpret_cast<float4*>(xs);
        xw[threadIdx.x]       = xr[threadIdx.x];
        xw[threadIdx.x + 128] = xr[threadIdx.x + 128];
    }

    const float s0 = (op_idx[o0]     == 0) ? 1.0f : -1.0f;
    const float s1 = (op_idx[o0 + 1] == 0) ? 1.0f : -1.0f;

    __syncthreads();
    const float4* xs4 = reinterpret_cast<const float4*>(xs);

    // ---- Steady state: proven depth-1 rotation, barrier-free.
    float red0 = half_row_min(A, xs4, lane, s0);

    #pragma unroll
    for (int j = 0; j < 4; ++j)                  // H2: row1 first half
        A[j] = __ldcs(rowp + 256 + j * 32 + lane);

    red0 = fminf(red0, half_row_min(Bv, xs4 + 128, lane, s0));

    #pragma unroll
    for (int j = 0; j < 4; ++j)                  // H3: row1 second half
        Bv[j] = __ldcs(rowp + 384 + j * 32 + lane);

    red0 = warp_min(red0);
    if (lane == 0)
        out[(size_t)b * O_DIM + o0] = s0 * red0;

    float red1 = half_row_min(A, xs4, lane, s1);
    red1 = fminf(red1, half_row_min(Bv, xs4 + 128, lane, s1));
    red1 = warp_min(red1);
    if (lane == 0)
        out[(size_t)b * O_DIM + o0 + 1] = s1 * red1;
}

extern "C" void kernel_launch(void* const* d_in, const int* in_sizes, int n_in,
                              void* d_out, int out_size)
{
    (void)in_sizes; (void)n_in; (void)out_size;
    const float* x      = (const float*)d_in[0];
    const int4*  et4    = (const int4*)d_in[1];
    const int*   op_idx = (const int*)d_in[2];
    float*       out    = (float*)d_out;

    const int blocks = B_DIM * GROUPS_PER_B;    // 8192
    ffcl_kernel<<<blocks, THREADS>>>(x, et4, op_idx, out);
}